// round 4
// baseline (speedup 1.0000x reference)
#include <cuda_runtime.h>

// axon_layer: dual-exponential PSP scan.
//   m_t = m_{t-1}*dm + x_t ; s_t = s_{t-1}*ds + x_t ; psp_t = (m_t - s_t)*v0
// Thread-per-row sequential scan over smem-staged tiles, depth-2 cp.async
// pipeline. Persistent-ish grid: exactly ngroups/2 blocks, each processing
// 2 row-groups, so every block does identical work and there is no wave tail.
//
// Inputs: [0] input_spikes f32 [B,F,T]  [1] decay_m f32 [F]
//         [2] decay_s f32 [F]           [3] v_0 f32 scalar
// Output: psps [B,F,T] then m_T [B,F] then s_T [B,F].

#define AX_THREADS 128
#define AX_ROWS    128
#define AX_T       400
#define AX_CH4     10            // float4 per chunk (40 floats)
#define AX_STRIDE  11            // padded row stride in float4 (odd -> no conflicts)
#define AX_NCHUNK  10
#define AX_RQ      (AX_T / 4)    // 100 float4 per full row

__device__ __forceinline__ void ax_cp_async16(void* smem_dst, const void* gmem_src) {
    unsigned saddr = (unsigned)__cvta_generic_to_shared(smem_dst);
    asm volatile("cp.async.cg.shared.global [%0], [%1], 16;\n"
                 :: "r"(saddr), "l"(gmem_src));
}
__device__ __forceinline__ void ax_cp_commit() {
    asm volatile("cp.async.commit_group;\n");
}
template <int N>
__device__ __forceinline__ void ax_cp_wait() {
    asm volatile("cp.async.wait_group %0;\n" :: "n"(N));
}

extern __shared__ float4 ax_smem[];   // 2 * AX_ROWS * AX_STRIDE float4 = 45056 B

__device__ __forceinline__ void ax_issue_chunk(const float4* __restrict__ gin,
                                               float4* __restrict__ buf,
                                               int ch, int tid)
{
#pragma unroll
    for (int i = 0; i < AX_CH4; ++i) {
        int idx = i * AX_THREADS + tid;          // 0..1279 linear over tile
        int r = idx / AX_CH4;
        int c = idx - r * AX_CH4;
        ax_cp_async16(&buf[r * AX_STRIDE + c],
                      &gin[(long long)r * AX_RQ + ch * AX_CH4 + c]);
    }
    ax_cp_commit();
}

__global__ void __launch_bounds__(AX_THREADS)
axon_pipe_kernel(const float* __restrict__ x,
                 const float* __restrict__ decay_m,
                 const float* __restrict__ decay_s,
                 const float* __restrict__ v0p,
                 float* __restrict__ out,
                 int F, long long n_rows, int units_per_block)
{
    const int tid = threadIdx.x;
    const float v0 = __ldg(v0p);

    float4* buf0 = ax_smem;
    float4* buf1 = ax_smem + AX_ROWS * AX_STRIDE;

    for (int u = 0; u < units_per_block; ++u) {
        const long long group = (long long)blockIdx.x + (long long)u * gridDim.x;
        const long long row0 = group * AX_ROWS;
        const long long my_row = row0 + tid;

        const float dm = __ldg(&decay_m[(int)(my_row % F)]);
        const float ds = __ldg(&decay_s[(int)(my_row % F)]);

        float m = 0.0f, s = 0.0f;

        const float4* __restrict__ gin  = (const float4*)x + row0 * AX_RQ;
        float4* __restrict__       gout = (float4*)out     + row0 * AX_RQ;

        // ---- prologue: chunks 0 and 1 in flight ----
        ax_issue_chunk(gin, buf0, 0, tid);
        ax_issue_chunk(gin, buf1, 1, tid);

        const int rbase = tid * AX_STRIDE;

        for (int ch = 0; ch < AX_NCHUNK; ++ch) {
            float4* buf = (ch & 1) ? buf1 : buf0;

            ax_cp_wait<1>();      // chunk ch resident; chunk ch+1 may still fly
            __syncthreads();

            // ---- sequential scan along T for this thread's row (in place) ----
#pragma unroll
            for (int t4 = 0; t4 < AX_CH4; ++t4) {
                float4 q = buf[rbase + t4];
                float4 o;
                m = fmaf(m, dm, q.x); s = fmaf(s, ds, q.x); o.x = (m - s) * v0;
                m = fmaf(m, dm, q.y); s = fmaf(s, ds, q.y); o.y = (m - s) * v0;
                m = fmaf(m, dm, q.z); s = fmaf(s, ds, q.z); o.z = (m - s) * v0;
                m = fmaf(m, dm, q.w); s = fmaf(s, ds, q.w); o.w = (m - s) * v0;
                buf[rbase + t4] = o;
            }
            __syncthreads();

            // ---- coalesced store of chunk ch ----
#pragma unroll
            for (int i = 0; i < AX_CH4; ++i) {
                int idx = i * AX_THREADS + tid;
                int r = idx / AX_CH4;
                int c = idx - r * AX_CH4;
                gout[(long long)r * AX_RQ + ch * AX_CH4 + c] = buf[r * AX_STRIDE + c];
            }
            __syncthreads();      // all smem reads done -> buffer reusable

            // ---- refill this buffer with chunk ch+2 ----
            if (ch + 2 < AX_NCHUNK) {
                ax_issue_chunk(gin, buf, ch + 2, tid);
            } else {
                ax_cp_commit();   // keep group counting uniform
            }
        }

        // ---- final states for this group ----
        const long long psps = n_rows * AX_T;
        out[psps + my_row]          = m;
        out[psps + n_rows + my_row] = s;
    }
}

extern "C" void kernel_launch(void* const* d_in, const int* in_sizes, int n_in,
                              void* d_out, int out_size)
{
    const float* x   = (const float*)d_in[0];
    const float* dmv = (const float*)d_in[1];
    const float* dsv = (const float*)d_in[2];
    const float* v0p = (const float*)d_in[3];
    float* out = (float*)d_out;

    const int F = in_sizes[1];                       // 4096
    const long long total = (long long)in_sizes[0];  // B*F*T
    const long long n_rows = total / AX_T;           // B*F = 131072
    const int ngroups = (int)(n_rows / AX_ROWS);     // 1024

    // Even split: every block handles exactly `upb` groups -> no wave tail.
    int upb = 2;
    int grid = ngroups / upb;                        // 512 (< 740 capacity)
    if (ngroups % upb) { upb = 1; grid = ngroups; }  // generic fallback

    const int smem_bytes = 2 * AX_ROWS * AX_STRIDE * (int)sizeof(float4);

    static bool attr_set = false;
    if (!attr_set) {
        cudaFuncSetAttribute(axon_pipe_kernel,
                             cudaFuncAttributeMaxDynamicSharedMemorySize,
                             smem_bytes);
        attr_set = true;
    }

    axon_pipe_kernel<<<grid, AX_THREADS, smem_bytes>>>(
        x, dmv, dsv, v0p, out, F, n_rows, upb);
}

// round 5
// speedup vs baseline: 1.0706x; 1.0706x over previous
#include <cuda_runtime.h>

// axon_layer: dual-exponential PSP scan.
//   m_t = m_{t-1}*dm + x_t ; s_t = s_{t-1}*ds + x_t ; psp_t = (m_t - s_t)*v0
// Thread-per-row sequential scan over smem-staged tiles, depth-2 cp.async
// pipeline. 64-row / 64-thread blocks (22.5 KB smem) so that ALL 1024 blocks
// are resident in a single wave (no wave-quantization tail); each block
// processes 2 row-groups (grid*2 == ngroups).
//
// Inputs: [0] input_spikes f32 [B,F,T]  [1] decay_m f32 [F]
//         [2] decay_s f32 [F]           [3] v_0 f32 scalar
// Output: psps [B,F,T] then m_T [B,F] then s_T [B,F].

#define AX_THREADS 64
#define AX_ROWS    64
#define AX_T       400
#define AX_CH4     10            // float4 per chunk (40 floats = 160 B/row)
#define AX_STRIDE  11            // padded row stride in float4 (odd -> no LDS conflicts)
#define AX_NCHUNK  10
#define AX_RQ      (AX_T / 4)    // 100 float4 per full row

__device__ __forceinline__ void ax_cp_async16(void* smem_dst, const void* gmem_src) {
    unsigned saddr = (unsigned)__cvta_generic_to_shared(smem_dst);
    asm volatile("cp.async.cg.shared.global [%0], [%1], 16;\n"
                 :: "r"(saddr), "l"(gmem_src));
}
__device__ __forceinline__ void ax_cp_commit() {
    asm volatile("cp.async.commit_group;\n");
}
template <int N>
__device__ __forceinline__ void ax_cp_wait() {
    asm volatile("cp.async.wait_group %0;\n" :: "n"(N));
}

extern __shared__ float4 ax_smem[];   // 2 * AX_ROWS * AX_STRIDE float4 = 22528 B

__device__ __forceinline__ void ax_issue_chunk(const float4* __restrict__ gin,
                                               float4* __restrict__ buf,
                                               int ch, int tid)
{
#pragma unroll
    for (int i = 0; i < AX_CH4; ++i) {
        int idx = i * AX_THREADS + tid;          // 0..639 linear over tile
        int r = idx / AX_CH4;
        int c = idx - r * AX_CH4;
        ax_cp_async16(&buf[r * AX_STRIDE + c],
                      &gin[(long long)r * AX_RQ + ch * AX_CH4 + c]);
    }
    ax_cp_commit();
}

__global__ void __launch_bounds__(AX_THREADS)
axon_pipe_kernel(const float* __restrict__ x,
                 const float* __restrict__ decay_m,
                 const float* __restrict__ decay_s,
                 const float* __restrict__ v0p,
                 float* __restrict__ out,
                 int F, long long n_rows, int units_per_block)
{
    const int tid = threadIdx.x;
    const float v0 = __ldg(v0p);

    float4* buf0 = ax_smem;
    float4* buf1 = ax_smem + AX_ROWS * AX_STRIDE;

    for (int u = 0; u < units_per_block; ++u) {
        const long long group = (long long)blockIdx.x * units_per_block + u;
        const long long row0 = group * AX_ROWS;
        const long long my_row = row0 + tid;

        const float dm = __ldg(&decay_m[(int)(my_row % F)]);
        const float ds = __ldg(&decay_s[(int)(my_row % F)]);

        float m = 0.0f, s = 0.0f;

        const float4* __restrict__ gin  = (const float4*)x + row0 * AX_RQ;
        float4* __restrict__       gout = (float4*)out     + row0 * AX_RQ;

        // ---- prologue: chunks 0 and 1 in flight ----
        ax_issue_chunk(gin, buf0, 0, tid);
        ax_issue_chunk(gin, buf1, 1, tid);

        const int rbase = tid * AX_STRIDE;

        for (int ch = 0; ch < AX_NCHUNK; ++ch) {
            float4* buf = (ch & 1) ? buf1 : buf0;

            ax_cp_wait<1>();      // chunk ch resident; chunk ch+1 may still fly
            __syncthreads();

            // ---- sequential scan along T for this thread's row (in place) ----
#pragma unroll
            for (int t4 = 0; t4 < AX_CH4; ++t4) {
                float4 q = buf[rbase + t4];
                float4 o;
                m = fmaf(m, dm, q.x); s = fmaf(s, ds, q.x); o.x = (m - s) * v0;
                m = fmaf(m, dm, q.y); s = fmaf(s, ds, q.y); o.y = (m - s) * v0;
                m = fmaf(m, dm, q.z); s = fmaf(s, ds, q.z); o.z = (m - s) * v0;
                m = fmaf(m, dm, q.w); s = fmaf(s, ds, q.w); o.w = (m - s) * v0;
                buf[rbase + t4] = o;
            }
            __syncthreads();

            // ---- coalesced store of chunk ch ----
#pragma unroll
            for (int i = 0; i < AX_CH4; ++i) {
                int idx = i * AX_THREADS + tid;
                int r = idx / AX_CH4;
                int c = idx - r * AX_CH4;
                gout[(long long)r * AX_RQ + ch * AX_CH4 + c] = buf[r * AX_STRIDE + c];
            }
            __syncthreads();      // all smem reads done -> buffer reusable

            // ---- refill this buffer with chunk ch+2 ----
            if (ch + 2 < AX_NCHUNK) {
                ax_issue_chunk(gin, buf, ch + 2, tid);
            } else {
                ax_cp_commit();   // keep group counting uniform
            }
        }

        // ---- final states for this group ----
        const long long psps = n_rows * AX_T;
        out[psps + my_row]          = m;
        out[psps + n_rows + my_row] = s;
    }
}

extern "C" void kernel_launch(void* const* d_in, const int* in_sizes, int n_in,
                              void* d_out, int out_size)
{
    const float* x   = (const float*)d_in[0];
    const float* dmv = (const float*)d_in[1];
    const float* dsv = (const float*)d_in[2];
    const float* v0p = (const float*)d_in[3];
    float* out = (float*)d_out;

    const int F = in_sizes[1];                       // 4096
    const long long total = (long long)in_sizes[0];  // B*F*T
    const long long n_rows = total / AX_T;           // B*F = 131072
    const int ngroups = (int)(n_rows / AX_ROWS);     // 2048 groups of 64 rows

    // Even split: every block handles exactly `upb` consecutive groups, and
    // the whole grid (1024 blocks @ 22.5 KB smem) is resident in ONE wave.
    int upb = 2;
    int grid = ngroups / upb;                        // 1024
    if (ngroups % upb) { upb = 1; grid = ngroups; }  // generic fallback

    const int smem_bytes = 2 * AX_ROWS * AX_STRIDE * (int)sizeof(float4);

    static bool attr_set = false;
    if (!attr_set) {
        cudaFuncSetAttribute(axon_pipe_kernel,
                             cudaFuncAttributeMaxDynamicSharedMemorySize,
                             smem_bytes);
        attr_set = true;
    }

    axon_pipe_kernel<<<grid, AX_THREADS, smem_bytes>>>(
        x, dmv, dsv, v0p, out, F, n_rows, upb);
}